// round 10
// baseline (speedup 1.0000x reference)
#include <cuda_runtime.h>
#include <cuda_fp16.h>

#define NB 8
#define CC 3
#define HD 1024
#define WD 1280
#define HS 800
#define WS 1280
#define HWD (HD*WD)
#define HWS (HS*WS)

// Output tile per CTA
#define TW 160
#define TH 28
#define TPX (TW*TH)          // 4480
#define NTHREADS 896
#define PXPT (TPX/NTHREADS)  // 5

// Staging rect worst-case (analytic span + margins + 4-alignment padding)
#define SW 380
#define SH 68
#define SMEM_BYTES (SW*SH*8)   // 206,720 B of uint2

__device__ __forceinline__ unsigned pack2(float a, float b)
{
    __half2 h = __floats2half2_rn(a, b);
    return *reinterpret_cast<unsigned*>(&h);
}

__device__ __forceinline__ float3 unpack_hwc(uint2 v)
{
    __half2 h01 = *reinterpret_cast<__half2*>(&v.x);
    __half2 h2p = *reinterpret_cast<__half2*>(&v.y);
    float2 f01 = __half22float2(h01);
    return make_float3(f01.x, f01.y, __low2float(h2p));
}

__global__ void __launch_bounds__(NTHREADS, 1)
warp_fused_kernel(const float* __restrict__ depth,
                  const float* __restrict__ src,
                  const float* __restrict__ abc,
                  const float* __restrict__ tr,
                  const float* __restrict__ pi,
                  float* __restrict__ out)
{
    extern __shared__ uint2 tile[];   // [SH][SW]
    __shared__ int s_rect[4];
    __shared__ int s_fits;

    const int tid = threadIdx.x;
    const int w0 = blockIdx.x * TW;
    const int h0 = blockIdx.y * TH;
    const int n  = blockIdx.z;

    const float tx = __ldg(tr + 0), ty = __ldg(tr + 1), tz = __ldg(tr + 2);
    const float fu = __ldg(pi + 0), fv = __ldg(pi + 1);
    const float du = __ldg(pi + 2), dv = __ldg(pi + 3);
    const float kx = (float)WS / (float)(WS - 1);
    const float ky = (float)HS / (float)(HS - 1);

    // ---- Phase 0 (warp 0): staging rect from 8 corner evals (uu/vv monotone) ----
    if (tid < 32) {
        int c3 = tid & 7;
        int wc = (c3 & 1) ? (w0 + TW - 1) : w0;
        int hc = (c3 & 2) ? min(h0 + TH - 1, HD - 1) : min(h0, HD - 1);
        float d = (c3 & 4) ? 1000.0f : 500.0f;
        int ci = hc * WD + wc;
        float a = __ldg(abc + ci);
        float b = __ldg(abc + HWD + ci);
        float c = __ldg(abc + 2 * HWD + ci);
        float denom = fmaf(c, d, tz);
        float inv = __fdividef(1.0f, denom);
        float uu = fmaf(fu, fmaf(a, d, tx) * inv, du);
        float vv = fmaf(fv, fmaf(b, d, ty) * inv, dv);
        float x = fmaf(uu, kx, -0.5f);
        float y = fmaf(vv, ky, -0.5f);

        float xmn = x, xmx = x, ymn = y, ymx = y;
#pragma unroll
        for (int s = 16; s >= 1; s >>= 1) {
            xmn = fminf(xmn, __shfl_xor_sync(0xFFFFFFFFu, xmn, s));
            xmx = fmaxf(xmx, __shfl_xor_sync(0xFFFFFFFFu, xmx, s));
            ymn = fminf(ymn, __shfl_xor_sync(0xFFFFFFFFu, ymn, s));
            ymx = fmaxf(ymx, __shfl_xor_sync(0xFFFFFFFFu, ymx, s));
        }
        if (tid == 0) {
            int rx0 = min(max((int)floorf(xmn) - 2, 0), WS - 1) & ~3;
            int rx1 = min(max((int)floorf(xmx) + 3, 0), WS - 1);
            int ry0 = min(max((int)floorf(ymn) - 2, 0), HS - 1);
            int ry1 = min(max((int)floorf(ymx) + 3, 0), HS - 1);
            int rw = ((rx1 - rx0 + 1) + 3) & ~3;   // mult of 4; never exceeds WS-rx0
            int rh = ry1 - ry0 + 1;
            s_rect[0] = rx0; s_rect[1] = ry0; s_rect[2] = rw; s_rect[3] = rh;
            s_fits = (rw <= SW && rh <= SH) ? 1 : 0;
        }
    }

    // ---- Phase B: precompute projections for this thread's 5 pixels ----
    float px[PXPT], py[PXPT];
#pragma unroll
    for (int k = 0; k < PXPT; k++) {
        int idx = k * NTHREADS + tid;
        int row = idx / TW;
        int col = idx - row * TW;
        int h = min(h0 + row, HD - 1);         // clamp for partial last y-block
        int pidx = h * WD + (w0 + col);

        float d = __ldg(depth + (size_t)n * HWD + pidx);
        float a = __ldg(abc + pidx);
        float b = __ldg(abc + HWD + pidx);
        float c = __ldg(abc + 2 * HWD + pidx);

        float denom = fmaf(c, d, tz);
        float inv = __fdividef(1.0f, denom);
        float uu = fmaf(fu, fmaf(a, d, tx) * inv, du);
        float vv = fmaf(fv, fmaf(b, d, ty) * inv, dv);
        float x = fmaf(uu, kx, -0.5f);
        float y = fmaf(vv, ky, -0.5f);
        px[k] = fminf(fmaxf(x, 0.0f), (float)(WS - 1));
        py[k] = fminf(fmaxf(y, 0.0f), (float)(HS - 1));
    }

    __syncthreads();
    const int rx0 = s_rect[0], ry0 = s_rect[1], rw = s_rect[2], rh = s_rect[3];
    const int fits = s_fits;
    const float* sbase = src + (size_t)n * CC * HWS;

    // ---- Phase 1: stage rect, vectorized + flat-balanced ----
    if (fits) {
        int rw4 = rw >> 2;
        int total4 = rh * rw4;
        for (int e = tid; e < total4; e += NTHREADS) {
            int y = e / rw4;
            int x4 = e - y * rw4;
            const float* r0 = sbase + (ry0 + y) * WS + rx0 + x4 * 4;
            float4 f0 = __ldg(reinterpret_cast<const float4*>(r0));
            float4 f1 = __ldg(reinterpret_cast<const float4*>(r0 + HWS));
            float4 f2 = __ldg(reinterpret_cast<const float4*>(r0 + 2 * HWS));
            uint4 lo, hi;
            lo.x = pack2(f0.x, f1.x); lo.y = pack2(f2.x, 0.0f);
            lo.z = pack2(f0.y, f1.y); lo.w = pack2(f2.y, 0.0f);
            hi.x = pack2(f0.z, f1.z); hi.y = pack2(f2.z, 0.0f);
            hi.z = pack2(f0.w, f1.w); hi.w = pack2(f2.w, 0.0f);
            uint4* dst = reinterpret_cast<uint4*>(tile + y * SW + x4 * 4);
            dst[0] = lo;
            dst[1] = hi;
        }
    }
    __syncthreads();

    // ---- Phase 2: bilinear from smem (pure LDS + FMA) ----
#pragma unroll
    for (int k = 0; k < PXPT; k++) {
        int idx = k * NTHREADS + tid;
        int row = idx / TW;
        int col = idx - row * TW;
        int h = h0 + row;
        if (h >= HD) continue;
        int pidx = h * WD + (w0 + col);

        float x = px[k], y = py[k];
        float x0f = floorf(x), y0f = floorf(y);
        float wx = x - x0f, wy = y - y0f;
        int x0 = (int)x0f, y0 = (int)y0f;
        int dx = (x0 < WS - 1) ? 1 : 0;

        float w00 = (1.0f - wy) * (1.0f - wx);
        float w01 = (1.0f - wy) * wx;
        float w10 = wy * (1.0f - wx);
        float w11 = wy * wx;

        float r0v, r1v, r2v;
        if (fits) {
            int sx = x0 - rx0;
            int sy = y0 - ry0;
            int dyo = (y0 < HS - 1) ? SW : 0;
            const uint2* sp = tile + sy * SW + sx;
            float3 f00 = unpack_hwc(sp[0]);
            float3 f01 = unpack_hwc(sp[dx]);
            float3 f10 = unpack_hwc(sp[dyo]);
            float3 f11 = unpack_hwc(sp[dyo + dx]);
            r0v = f00.x * w00 + f01.x * w01 + f10.x * w10 + f11.x * w11;
            r1v = f00.y * w00 + f01.y * w01 + f10.y * w10 + f11.y * w11;
            r2v = f00.z * w00 + f01.z * w01 + f10.z * w10 + f11.z * w11;
        } else {
            int dyo = (y0 < HS - 1) ? WS : 0;
            int p = y0 * WS + x0;
            const float* s0 = sbase;
            r0v = __ldg(s0 + p) * w00 + __ldg(s0 + p + dx) * w01
                + __ldg(s0 + p + dyo) * w10 + __ldg(s0 + p + dyo + dx) * w11;
            const float* s1 = sbase + HWS;
            r1v = __ldg(s1 + p) * w00 + __ldg(s1 + p + dx) * w01
                + __ldg(s1 + p + dyo) * w10 + __ldg(s1 + p + dyo + dx) * w11;
            const float* s2 = sbase + 2 * HWS;
            r2v = __ldg(s2 + p) * w00 + __ldg(s2 + p + dx) * w01
                + __ldg(s2 + p + dyo) * w10 + __ldg(s2 + p + dyo + dx) * w11;
        }

        float* op = out + (size_t)n * CC * HWD + pidx;
        op[0]       = r0v;
        op[HWD]     = r1v;
        op[2 * HWD] = r2v;
    }
}

extern "C" void kernel_launch(void* const* d_in, const int* in_sizes, int n_in,
                              void* d_out, int out_size)
{
    const float* depth = (const float*)d_in[0];
    const float* src   = (const float*)d_in[1];
    const float* abc   = (const float*)d_in[2];
    const float* tr    = (const float*)d_in[3];
    const float* pi    = (const float*)d_in[4];
    float* out = (float*)d_out;

    cudaFuncSetAttribute(warp_fused_kernel,
                         cudaFuncAttributeMaxDynamicSharedMemorySize, SMEM_BYTES);

    dim3 grid(WD / TW, (HD + TH - 1) / TH, NB);   // 8 x 37 x 8
    warp_fused_kernel<<<grid, NTHREADS, SMEM_BYTES>>>(depth, src, abc, tr, pi, out);
}

// round 11
// speedup vs baseline: 1.1157x; 1.1157x over previous
#include <cuda_runtime.h>
#include <cuda_fp16.h>

#define NB 8
#define CC 3
#define HD 1024
#define WD 1280
#define HS 800
#define WS 1280
#define HWD (HD*WD)
#define HWS (HS*WS)

// Output tile per CTA
#define TW 128
#define TH 64
#define TPX (TW*TH)            // 8192
#define NTHREADS 1024
#define GRP (TPX/4/NTHREADS)   // 2 groups of 4 px per thread

// Staging rect worst-case (analytic: u-span 196 depth + 1.12*127 slope + margin;
// v-span 24.4 depth + 1.004*63 slope + 8.2 w-coupling + margin)
#define SW 352
#define SH 106
// smem: tileA = uint32 h01[SH*SW] (4B/px), tileB = __half h2[SH*SW] (2B/px)
#define SMEM_BYTES (SW*SH*6)   // 223,872 B

__device__ __forceinline__ unsigned pack2(float a, float b)
{
    __half2 h = __floats2half2_rn(a, b);
    return *reinterpret_cast<unsigned*>(&h);
}

__global__ void __launch_bounds__(NTHREADS, 1)
warp_fused_kernel(const float* __restrict__ depth,
                  const float* __restrict__ src,
                  const float* __restrict__ abc,
                  const float* __restrict__ tr,
                  const float* __restrict__ pi,
                  float* __restrict__ out)
{
    extern __shared__ unsigned smem_raw[];
    unsigned* tileA = smem_raw;                                   // h01 packed
    __half*  tileB = reinterpret_cast<__half*>(smem_raw + SW * SH); // h2
    __shared__ int s_rect[4];
    __shared__ int s_fits;

    const int tid = threadIdx.x;
    const int w0 = blockIdx.x * TW;
    const int h0 = blockIdx.y * TH;
    const int n  = blockIdx.z;

    const float tx = __ldg(tr + 0), ty = __ldg(tr + 1), tz = __ldg(tr + 2);
    const float fu = __ldg(pi + 0), fv = __ldg(pi + 1);
    const float du = __ldg(pi + 2), dv = __ldg(pi + 3);
    const float kx = (float)WS / (float)(WS - 1);
    const float ky = (float)HS / (float)(HS - 1);

    // ---- Phase 0 (warp 0): staging rect from 8 corner evals (uu/vv monotone) ----
    if (tid < 32) {
        int c3 = tid & 7;
        int wc = (c3 & 1) ? (w0 + TW - 1) : w0;
        int hc = (c3 & 2) ? (h0 + TH - 1) : h0;
        float d = (c3 & 4) ? 1000.0f : 500.0f;
        int ci = hc * WD + wc;
        float a = __ldg(abc + ci);
        float b = __ldg(abc + HWD + ci);
        float c = __ldg(abc + 2 * HWD + ci);
        float denom = fmaf(c, d, tz);
        float inv = __fdividef(1.0f, denom);
        float uu = fmaf(fu, fmaf(a, d, tx) * inv, du);
        float vv = fmaf(fv, fmaf(b, d, ty) * inv, dv);
        float x = fmaf(uu, kx, -0.5f);
        float y = fmaf(vv, ky, -0.5f);

        float xmn = x, xmx = x, ymn = y, ymx = y;
#pragma unroll
        for (int s = 16; s >= 1; s >>= 1) {
            xmn = fminf(xmn, __shfl_xor_sync(0xFFFFFFFFu, xmn, s));
            xmx = fmaxf(xmx, __shfl_xor_sync(0xFFFFFFFFu, xmx, s));
            ymn = fminf(ymn, __shfl_xor_sync(0xFFFFFFFFu, ymn, s));
            ymx = fmaxf(ymx, __shfl_xor_sync(0xFFFFFFFFu, ymx, s));
        }
        if (tid == 0) {
            int rx0 = min(max((int)floorf(xmn) - 2, 0), WS - 1) & ~3;
            int rx1 = min(max((int)floorf(xmx) + 3, 0), WS - 1);
            int ry0 = min(max((int)floorf(ymn) - 2, 0), HS - 1);
            int ry1 = min(max((int)floorf(ymx) + 3, 0), HS - 1);
            int rw = ((rx1 - rx0 + 1) + 3) & ~3;   // mult of 4
            int rh = ry1 - ry0 + 1;
            s_rect[0] = rx0; s_rect[1] = ry0; s_rect[2] = rw; s_rect[3] = rh;
            s_fits = (rw <= SW && rh <= SH) ? 1 : 0;
        }
    }
    __syncthreads();

    const int rx0 = s_rect[0], ry0 = s_rect[1], rw = s_rect[2], rh = s_rect[3];
    const int fits = s_fits;
    const float* sbase = src + (size_t)n * CC * HWS;

    // ---- Phase 1: stage rect -> split fp16 arrays, vectorized ----
    if (fits) {
        int rw4 = rw >> 2;
        int total4 = rh * rw4;
        for (int e = tid; e < total4; e += NTHREADS) {
            int y = e / rw4;
            int x4 = e - y * rw4;
            const float* r0 = sbase + (ry0 + y) * WS + rx0 + x4 * 4;
            float4 f0 = __ldg(reinterpret_cast<const float4*>(r0));
            float4 f1 = __ldg(reinterpret_cast<const float4*>(r0 + HWS));
            float4 f2 = __ldg(reinterpret_cast<const float4*>(r0 + 2 * HWS));
            uint4 va;
            va.x = pack2(f0.x, f1.x);
            va.y = pack2(f0.y, f1.y);
            va.z = pack2(f0.z, f1.z);
            va.w = pack2(f0.w, f1.w);
            int o = y * SW + x4 * 4;
            *reinterpret_cast<uint4*>(tileA + o) = va;
            __half2 b01 = __floats2half2_rn(f2.x, f2.y);
            __half2 b23 = __floats2half2_rn(f2.z, f2.w);
            uint2 vb;
            vb.x = *reinterpret_cast<unsigned*>(&b01);
            vb.y = *reinterpret_cast<unsigned*>(&b23);
            *reinterpret_cast<uint2*>(tileB + o) = vb;
        }
    }
    __syncthreads();

    // ---- Phase 2: project + bilinear, 4 consecutive px per thread ----
#pragma unroll
    for (int g = 0; g < GRP; g++) {
        int grp = g * NTHREADS + tid;           // group index over TPX/4
        int row = grp / (TW / 4);
        int cg  = grp - row * (TW / 4);
        int h = h0 + row;
        int pidx = h * WD + w0 + cg * 4;

        const float* dp = depth + (size_t)n * HWD + pidx;
        float4 d4 = __ldg(reinterpret_cast<const float4*>(dp));
        float4 a4 = __ldg(reinterpret_cast<const float4*>(abc + pidx));
        float4 b4 = __ldg(reinterpret_cast<const float4*>(abc + HWD + pidx));
        float4 c4 = __ldg(reinterpret_cast<const float4*>(abc + 2 * HWD + pidx));

        float r0a[4], r1a[4], r2a[4];
        const float* dd = reinterpret_cast<const float*>(&d4);
        const float* aa = reinterpret_cast<const float*>(&a4);
        const float* bb = reinterpret_cast<const float*>(&b4);
        const float* cc = reinterpret_cast<const float*>(&c4);

#pragma unroll
        for (int j = 0; j < 4; j++) {
            float d = dd[j];
            float denom = fmaf(cc[j], d, tz);
            float inv = __fdividef(1.0f, denom);
            float uu = fmaf(fu, fmaf(aa[j], d, tx) * inv, du);
            float vv = fmaf(fv, fmaf(bb[j], d, ty) * inv, dv);
            float x = fmaf(uu, kx, -0.5f);
            float y = fmaf(vv, ky, -0.5f);
            x = fminf(fmaxf(x, 0.0f), (float)(WS - 1));
            y = fminf(fmaxf(y, 0.0f), (float)(HS - 1));

            float x0f = floorf(x), y0f = floorf(y);
            float wx = x - x0f, wy = y - y0f;
            int x0 = (int)x0f, y0 = (int)y0f;
            int dx = (x0 < WS - 1) ? 1 : 0;

            float w00 = (1.0f - wy) * (1.0f - wx);
            float w01 = (1.0f - wy) * wx;
            float w10 = wy * (1.0f - wx);
            float w11 = wy * wx;

            if (fits) {
                int dyo = (y0 < HS - 1) ? SW : 0;
                int o = (y0 - ry0) * SW + (x0 - rx0);
                unsigned p00 = tileA[o];
                unsigned p01 = tileA[o + dx];
                unsigned p10 = tileA[o + dyo];
                unsigned p11 = tileA[o + dyo + dx];
                float2 f00 = __half22float2(*reinterpret_cast<__half2*>(&p00));
                float2 f01 = __half22float2(*reinterpret_cast<__half2*>(&p01));
                float2 f10 = __half22float2(*reinterpret_cast<__half2*>(&p10));
                float2 f11 = __half22float2(*reinterpret_cast<__half2*>(&p11));
                r0a[j] = f00.x * w00 + f01.x * w01 + f10.x * w10 + f11.x * w11;
                r1a[j] = f00.y * w00 + f01.y * w01 + f10.y * w10 + f11.y * w11;
                float g00 = __half2float(tileB[o]);
                float g01 = __half2float(tileB[o + dx]);
                float g10 = __half2float(tileB[o + dyo]);
                float g11 = __half2float(tileB[o + dyo + dx]);
                r2a[j] = g00 * w00 + g01 * w01 + g10 * w10 + g11 * w11;
            } else {
                int dyo = (y0 < HS - 1) ? WS : 0;
                int p = y0 * WS + x0;
                const float* s0 = sbase;
                r0a[j] = __ldg(s0 + p) * w00 + __ldg(s0 + p + dx) * w01
                       + __ldg(s0 + p + dyo) * w10 + __ldg(s0 + p + dyo + dx) * w11;
                const float* s1 = sbase + HWS;
                r1a[j] = __ldg(s1 + p) * w00 + __ldg(s1 + p + dx) * w01
                       + __ldg(s1 + p + dyo) * w10 + __ldg(s1 + p + dyo + dx) * w11;
                const float* s2 = sbase + 2 * HWS;
                r2a[j] = __ldg(s2 + p) * w00 + __ldg(s2 + p + dx) * w01
                       + __ldg(s2 + p + dyo) * w10 + __ldg(s2 + p + dyo + dx) * w11;
            }
        }

        float* op = out + (size_t)n * CC * HWD + pidx;
        *reinterpret_cast<float4*>(op)           = make_float4(r0a[0], r0a[1], r0a[2], r0a[3]);
        *reinterpret_cast<float4*>(op + HWD)     = make_float4(r1a[0], r1a[1], r1a[2], r1a[3]);
        *reinterpret_cast<float4*>(op + 2 * HWD) = make_float4(r2a[0], r2a[1], r2a[2], r2a[3]);
    }
}

extern "C" void kernel_launch(void* const* d_in, const int* in_sizes, int n_in,
                              void* d_out, int out_size)
{
    const float* depth = (const float*)d_in[0];
    const float* src   = (const float*)d_in[1];
    const float* abc   = (const float*)d_in[2];
    const float* tr    = (const float*)d_in[3];
    const float* pi    = (const float*)d_in[4];
    float* out = (float*)d_out;

    cudaFuncSetAttribute(warp_fused_kernel,
                         cudaFuncAttributeMaxDynamicSharedMemorySize, SMEM_BYTES);

    dim3 grid(WD / TW, HD / TH, NB);   // 10 x 16 x 8 = 1280 CTAs
    warp_fused_kernel<<<grid, NTHREADS, SMEM_BYTES>>>(depth, src, abc, tr, pi, out);
}